// round 11
// baseline (speedup 1.0000x reference)
#include <cuda_runtime.h>
#include <math.h>

#define BB 4
#define LQ 1024
#define LK 2048
#define EE 768
#define HH 16
#define HD 48
#define MQ (BB*LQ)
#define MK (BB*LK)
#define SPITCH 130
#define SCALE 0.14433756729740643f   /* 1/sqrt(48) */

// ---------------- static scratch ----------------
__device__ float g_qp[MQ*EE];
__device__ float g_kp[MK*EE];
__device__ float g_vp[MK*EE];
__device__ float g_ctx[MQ*EE];
__device__ float g_attnout[MQ*EE];
__device__ float g_qmean[BB*EE];
__device__ float g_kmean[BB*EE];
__device__ float g_sf[BB];
__device__ float g_gv[BB];
__device__ float g_rowm[BB*HH*LQ];     // scaled-domain row max
__device__ float g_rowinv[BB*HH*LQ];   // 1/sum

// ---------------- tf32 helpers ----------------
__device__ __forceinline__ unsigned f2tf(float x) {
    unsigned r; asm("cvt.rna.tf32.f32 %0, %1;" : "=r"(r) : "f"(x)); return r;
}
__device__ __forceinline__ void mma_tf32(float* c, unsigned a0, unsigned a1, unsigned a2, unsigned a3,
                                         unsigned b0, unsigned b1) {
    asm volatile("mma.sync.aligned.m16n8k8.row.col.f32.tf32.tf32.f32 "
                 "{%0,%1,%2,%3},{%4,%5,%6,%7},{%8,%9},{%0,%1,%2,%3};"
                 : "+f"(c[0]), "+f"(c[1]), "+f"(c[2]), "+f"(c[3])
                 : "r"(a0), "r"(a1), "r"(a2), "r"(a3), "r"(b0), "r"(b1));
}

// ---------------- mean over sequence ----------------
__global__ void mean_kernel(const float* __restrict__ x, int L, int which) {
    int idx = blockIdx.x * blockDim.x + threadIdx.x;
    if (idx >= BB * EE) return;
    int b = idx / EE, e = idx % EE;
    const float* p = x + (size_t)b * L * EE + e;
    float s = 0.f;
    for (int l = 0; l < L; l++) s += p[(size_t)l * EE];
    (which ? g_kmean : g_qmean)[idx] = s / (float)L;
}

// ---------------- controller MLP ----------------
__global__ void mlp_kernel(const float* __restrict__ Wp1, const float* __restrict__ bp1,
                           const float* __restrict__ Wp2, const float* __restrict__ bp2,
                           const float* __restrict__ Wp3, const float* __restrict__ bp3,
                           float* __restrict__ out_tail) {
    int b = blockIdx.x;
    int t = threadIdx.x;
    __shared__ float pin[2*EE];
    __shared__ float sh1[EE];
    __shared__ float sh2[EE/2];
    __shared__ float spred[3];
    pin[t]      = g_qmean[b*EE + t];
    pin[EE + t] = g_kmean[b*EE + t];
    __syncthreads();
    {
        float acc = bp1[t];
        const float* w = Wp1 + (size_t)t * (2*EE);
        for (int j = 0; j < 2*EE; j++) acc = fmaf(pin[j], w[j], acc);
        sh1[t] = fmaxf(acc, 0.f);
    }
    __syncthreads();
    if (t < EE/2) {
        float acc = bp2[t];
        const float* w = Wp2 + (size_t)t * EE;
        for (int j = 0; j < EE; j++) acc = fmaf(sh1[j], w[j], acc);
        sh2[t] = fmaxf(acc, 0.f);
    }
    __syncthreads();
    if (t < 3) {
        float acc = bp3[t];
        const float* w = Wp3 + t * (EE/2);
        for (int j = 0; j < EE/2; j++) acc = fmaf(sh2[j], w[j], acc);
        spred[t] = acc;
    }
    __syncthreads();
    if (t == 0) {
        float s0 = 1.f / (1.f + expf(-spred[0]));
        float nh = rintf(s0 * (float)(HH - 1) + 1.f);
        float sf = (1.f / (1.f + expf(-spred[1]))) * 0.5f + 0.5f;
        float gv = 1.f / (1.f + expf(-spred[2]));
        g_sf[b] = sf; g_gv[b] = gv;
        out_tail[b]        = nh;
        out_tail[BB + b]   = sf;
        out_tail[2*BB + b] = gv;
    }
}

// ---------------- tf32 GEMM: C[M,N] = A[M,K] @ W[N,K]^T + bias ----------------
__global__ __launch_bounds__(256, 2)
void gemm_tf32_kernel(const float* __restrict__ A, const float* __restrict__ W,
                      const float* __restrict__ bias, float* __restrict__ C,
                      int M, int N, int K) {
    __shared__ unsigned As[2][16][SPITCH];
    __shared__ unsigned Bs[2][16][SPITCH];
    const int tid = threadIdx.x;
    const int wid = tid >> 5, lane = tid & 31;
    const int grp = lane >> 2, tig = lane & 3;
    const int wm = wid & 1, wn = wid >> 1;
    const int m0 = blockIdx.y * 128, n0 = blockIdx.x * 128;
    const int row = tid >> 1, colh = (tid & 1) * 8;
    const float* Ap = A + (size_t)(m0 + row) * K + colh;
    const float* Wp = W + (size_t)(n0 + row) * K + colh;
    float acc[4][4][4] = {};
    const int T = K >> 4;
    float4 av0 = *(const float4*)Ap, av1 = *(const float4*)(Ap + 4);
    float4 wv0 = *(const float4*)Wp, wv1 = *(const float4*)(Wp + 4);
    int buf = 0;
    for (int t = 0; t < T; t++) {
        As[buf][colh+0][row] = f2tf(av0.x); As[buf][colh+1][row] = f2tf(av0.y);
        As[buf][colh+2][row] = f2tf(av0.z); As[buf][colh+3][row] = f2tf(av0.w);
        As[buf][colh+4][row] = f2tf(av1.x); As[buf][colh+5][row] = f2tf(av1.y);
        As[buf][colh+6][row] = f2tf(av1.z); As[buf][colh+7][row] = f2tf(av1.w);
        Bs[buf][colh+0][row] = f2tf(wv0.x); Bs[buf][colh+1][row] = f2tf(wv0.y);
        Bs[buf][colh+2][row] = f2tf(wv0.z); Bs[buf][colh+3][row] = f2tf(wv0.w);
        Bs[buf][colh+4][row] = f2tf(wv1.x); Bs[buf][colh+5][row] = f2tf(wv1.y);
        Bs[buf][colh+6][row] = f2tf(wv1.z); Bs[buf][colh+7][row] = f2tf(wv1.w);
        __syncthreads();
        if (t + 1 < T) {
            av0 = *(const float4*)(Ap + (t+1)*16); av1 = *(const float4*)(Ap + (t+1)*16 + 4);
            wv0 = *(const float4*)(Wp + (t+1)*16); wv1 = *(const float4*)(Wp + (t+1)*16 + 4);
        }
        #pragma unroll
        for (int ks = 0; ks < 2; ks++) {
            const int k0 = ks * 8;
            unsigned af[4][4], bf[4][2];
            #pragma unroll
            for (int mi = 0; mi < 4; mi++) {
                int m = wm*64 + mi*16;
                af[mi][0] = As[buf][k0+tig  ][m+grp];
                af[mi][1] = As[buf][k0+tig  ][m+grp+8];
                af[mi][2] = As[buf][k0+tig+4][m+grp];
                af[mi][3] = As[buf][k0+tig+4][m+grp+8];
            }
            #pragma unroll
            for (int ni = 0; ni < 4; ni++) {
                int n = wn*32 + ni*8;
                bf[ni][0] = Bs[buf][k0+tig  ][n+grp];
                bf[ni][1] = Bs[buf][k0+tig+4][n+grp];
            }
            #pragma unroll
            for (int mi = 0; mi < 4; mi++)
                #pragma unroll
                for (int ni = 0; ni < 4; ni++)
                    mma_tf32(acc[mi][ni], af[mi][0], af[mi][1], af[mi][2], af[mi][3],
                             bf[ni][0], bf[ni][1]);
        }
        buf ^= 1;
    }
    #pragma unroll
    for (int mi = 0; mi < 4; mi++) {
        int m = m0 + wm*64 + mi*16 + grp;
        #pragma unroll
        for (int ni = 0; ni < 4; ni++) {
            int n = n0 + wn*32 + ni*8 + 2*tig;
            float b0 = bias[n], b1 = bias[n+1];
            float2 o;
            o.x = acc[mi][ni][0] + b0; o.y = acc[mi][ni][1] + b1;
            *(float2*)&C[(size_t)m * N + n] = o;
            o.x = acc[mi][ni][2] + b0; o.y = acc[mi][ni][3] + b1;
            *(float2*)&C[(size_t)(m+8) * N + n] = o;
        }
    }
}

// ================= FLASH ATTENTION (no score materialization) =================
// smem layout (unsigned words):
//   Qs [48][136]  off 0      (6528)
//   Ks [48][136]  off 6528   (6528)
//   Vs [128][56]  off 13056  (7168)
//   Ps [128][132] off 20224  (16896)
//   Ms (128 bytes) off 37120 words
#define FL_QS 0
#define FL_KS 6528
#define FL_VS 13056
#define FL_PS 20224
#define FL_MS 37120
#define FL_SMEM ((37120 + 32) * 4)

__global__ __launch_bounds__(256)
void flash_kernel(const unsigned char* __restrict__ mask) {
    extern __shared__ unsigned sm[];
    unsigned* Qs = sm + FL_QS;
    unsigned* Ks = sm + FL_KS;
    unsigned* Vs = sm + FL_VS;
    unsigned* Ps = sm + FL_PS;
    unsigned char* Ms = (unsigned char*)(sm + FL_MS);

    const int bh = blockIdx.y, b = bh >> 4, h = bh & 15;
    const int q0 = blockIdx.x * 128;
    const int tid = threadIdx.x;
    const int wid = tid >> 5, lane = tid & 31;
    const int grp = lane >> 2, tig = lane & 3;
    const int qw = wid * 16;

    // load Q tile (transposed [d][q], tf32)
    {
        const float* qb = g_qp + (size_t)(b*LQ + q0) * EE + h*HD;
        for (int i = tid; i < 128*12; i += 256) {
            int q = i & 127, dc = i >> 7;
            float4 v = *(const float4*)(qb + (size_t)q * EE + dc*4);
            Qs[(dc*4+0)*136 + q] = f2tf(v.x);
            Qs[(dc*4+1)*136 + q] = f2tf(v.y);
            Qs[(dc*4+2)*136 + q] = f2tf(v.z);
            Qs[(dc*4+3)*136 + q] = f2tf(v.w);
        }
    }

    float o[6][4] = {};
    float m0 = -3.4e38f, m1 = -3.4e38f;
    float s0 = 0.f, s1 = 0.f;

    for (int kt = 0; kt < LK/128; kt++) {
        __syncthreads();
        // load K tile [d][k], V tile [k][d], mask bytes
        const float* kb = g_kp + (size_t)(b*LK + kt*128) * EE + h*HD;
        const float* vb = g_vp + (size_t)(b*LK + kt*128) * EE + h*HD;
        for (int i = tid; i < 128*12; i += 256) {
            int k = i & 127, dc = i >> 7;
            float4 v = *(const float4*)(kb + (size_t)k * EE + dc*4);
            Ks[(dc*4+0)*136 + k] = f2tf(v.x);
            Ks[(dc*4+1)*136 + k] = f2tf(v.y);
            Ks[(dc*4+2)*136 + k] = f2tf(v.z);
            Ks[(dc*4+3)*136 + k] = f2tf(v.w);
            float4 w = *(const float4*)(vb + (size_t)k * EE + dc*4);
            Vs[k*56 + dc*4+0] = f2tf(w.x);
            Vs[k*56 + dc*4+1] = f2tf(w.y);
            Vs[k*56 + dc*4+2] = f2tf(w.z);
            Vs[k*56 + dc*4+3] = f2tf(w.w);
        }
        if (tid < 128) Ms[tid] = mask[b*LK + kt*128 + tid];
        __syncthreads();

        // S = Q @ K^T  (warp: 16 q rows x 128 k cols)
        float sacc[16][4] = {};
        #pragma unroll
        for (int slab = 0; slab < 6; slab++) {
            unsigned a0 = Qs[(slab*8+tig  )*136 + qw+grp];
            unsigned a1 = Qs[(slab*8+tig  )*136 + qw+grp+8];
            unsigned a2 = Qs[(slab*8+tig+4)*136 + qw+grp];
            unsigned a3 = Qs[(slab*8+tig+4)*136 + qw+grp+8];
            #pragma unroll
            for (int ni = 0; ni < 16; ni++) {
                unsigned b0 = Ks[(slab*8+tig  )*136 + ni*8+grp];
                unsigned b1 = Ks[(slab*8+tig+4)*136 + ni*8+grp];
                mma_tf32(sacc[ni], a0, a1, a2, a3, b0, b1);
            }
        }

        // scale + mask + tile max
        float tm0 = -3.4e38f, tm1 = -3.4e38f;
        #pragma unroll
        for (int ni = 0; ni < 16; ni++) {
            int kc = ni*8 + 2*tig;
            bool mk0 = Ms[kc], mk1 = Ms[kc+1];
            sacc[ni][0] = mk0 ? -1e30f : sacc[ni][0]*SCALE;
            sacc[ni][1] = mk1 ? -1e30f : sacc[ni][1]*SCALE;
            sacc[ni][2] = mk0 ? -1e30f : sacc[ni][2]*SCALE;
            sacc[ni][3] = mk1 ? -1e30f : sacc[ni][3]*SCALE;
            tm0 = fmaxf(tm0, fmaxf(sacc[ni][0], sacc[ni][1]));
            tm1 = fmaxf(tm1, fmaxf(sacc[ni][2], sacc[ni][3]));
        }
        tm0 = fmaxf(tm0, __shfl_xor_sync(0xffffffffu, tm0, 1));
        tm0 = fmaxf(tm0, __shfl_xor_sync(0xffffffffu, tm0, 2));
        tm1 = fmaxf(tm1, __shfl_xor_sync(0xffffffffu, tm1, 1));
        tm1 = fmaxf(tm1, __shfl_xor_sync(0xffffffffu, tm1, 2));

        float mn0 = fmaxf(m0, tm0), mn1 = fmaxf(m1, tm1);
        float f0 = __expf(m0 - mn0), f1 = __expf(m1 - mn1);
        m0 = mn0; m1 = mn1;
        s0 *= f0; s1 *= f1;
        #pragma unroll
        for (int ni = 0; ni < 6; ni++) {
            o[ni][0] *= f0; o[ni][1] *= f0;
            o[ni][2] *= f1; o[ni][3] *= f1;
        }

        // p = exp(s - m), partial sums, stage P to smem
        float ps0 = 0.f, ps1 = 0.f;
        #pragma unroll
        for (int ni = 0; ni < 16; ni++) {
            float p0 = __expf(sacc[ni][0] - mn0);
            float p1 = __expf(sacc[ni][1] - mn0);
            float p2 = __expf(sacc[ni][2] - mn1);
            float p3 = __expf(sacc[ni][3] - mn1);
            ps0 += p0 + p1; ps1 += p2 + p3;
            int kc = ni*8 + 2*tig;
            Ps[(qw+grp  )*132 + kc  ] = f2tf(p0);
            Ps[(qw+grp  )*132 + kc+1] = f2tf(p1);
            Ps[(qw+grp+8)*132 + kc  ] = f2tf(p2);
            Ps[(qw+grp+8)*132 + kc+1] = f2tf(p3);
        }
        s0 += ps0; s1 += ps1;
        __syncthreads();

        // O += P @ V
        #pragma unroll
        for (int slab = 0; slab < 16; slab++) {
            unsigned a0 = Ps[(qw+grp  )*132 + slab*8+tig];
            unsigned a1 = Ps[(qw+grp+8)*132 + slab*8+tig];
            unsigned a2 = Ps[(qw+grp  )*132 + slab*8+tig+4];
            unsigned a3 = Ps[(qw+grp+8)*132 + slab*8+tig+4];
            #pragma unroll
            for (int ni = 0; ni < 6; ni++) {
                unsigned b0 = Vs[(slab*8+tig  )*56 + ni*8+grp];
                unsigned b1 = Vs[(slab*8+tig+4)*56 + ni*8+grp];
                mma_tf32(o[ni], a0, a1, a2, a3, b0, b1);
            }
        }
    }

    // finalize sums (quad reduce), write ctx and stats
    s0 += __shfl_xor_sync(0xffffffffu, s0, 1);
    s0 += __shfl_xor_sync(0xffffffffu, s0, 2);
    s1 += __shfl_xor_sync(0xffffffffu, s1, 1);
    s1 += __shfl_xor_sync(0xffffffffu, s1, 2);
    float inv0 = 1.f / s0, inv1 = 1.f / s1;

    float* cb = g_ctx + (size_t)(b*LQ + q0 + qw) * EE + h*HD;
    #pragma unroll
    for (int ni = 0; ni < 6; ni++) {
        int d = ni*8 + 2*tig;
        float2 v0; v0.x = o[ni][0]*inv0; v0.y = o[ni][1]*inv0;
        *(float2*)&cb[(size_t)grp * EE + d] = v0;
        float2 v1; v1.x = o[ni][2]*inv1; v1.y = o[ni][3]*inv1;
        *(float2*)&cb[(size_t)(grp+8) * EE + d] = v1;
    }
    if (tig == 0) {
        int r = bh*LQ + q0 + qw;
        g_rowm[r+grp]     = m0;  g_rowinv[r+grp]     = inv0;
        g_rowm[r+grp+8]   = m1;  g_rowinv[r+grp+8]   = inv1;
    }
}

// ================= attn_weights: recompute scores, mean over heads =================
// smem: Qs [48][136], Ks [48][136]
#define AM_SMEM ((6528*2) * 4)
__global__ __launch_bounds__(256)
void attnmean2_kernel(const unsigned char* __restrict__ mask, float* __restrict__ aw) {
    extern __shared__ unsigned sm[];
    unsigned* Qs = sm;
    unsigned* Ks = sm + 6528;
    const int b = blockIdx.z;
    const int q0 = blockIdx.y * 128, k0g = blockIdx.x * 128;
    const int tid = threadIdx.x;
    const int wid = tid >> 5, lane = tid & 31;
    const int grp = lane >> 2, tig = lane & 3;
    const int qw = wid * 16;

    // per-lane mask bits for its 32 columns
    unsigned mbits = 0;
    #pragma unroll
    for (int ni = 0; ni < 16; ni++) {
        int kc = k0g + ni*8 + 2*tig;
        if (mask[b*LK + kc  ]) mbits |= 1u << (2*ni);
        if (mask[b*LK + kc+1]) mbits |= 1u << (2*ni+1);
    }

    float aacc[16][4] = {};
    for (int h = 0; h < HH; h++) {
        __syncthreads();
        const float* qb = g_qp + (size_t)(b*LQ + q0) * EE + h*HD;
        const float* kb = g_kp + (size_t)(b*LK + k0g) * EE + h*HD;
        for (int i = tid; i < 128*12; i += 256) {
            int r = i & 127, dc = i >> 7;
            float4 v = *(const float4*)(qb + (size_t)r * EE + dc*4);
            Qs[(dc*4+0)*136 + r] = f2tf(v.x);
            Qs[(dc*4+1)*136 + r] = f2tf(v.y);
            Qs[(dc*4+2)*136 + r] = f2tf(v.z);
            Qs[(dc*4+3)*136 + r] = f2tf(v.w);
            float4 w = *(const float4*)(kb + (size_t)r * EE + dc*4);
            Ks[(dc*4+0)*136 + r] = f2tf(w.x);
            Ks[(dc*4+1)*136 + r] = f2tf(w.y);
            Ks[(dc*4+2)*136 + r] = f2tf(w.z);
            Ks[(dc*4+3)*136 + r] = f2tf(w.w);
        }
        __syncthreads();

        float sacc[16][4] = {};
        #pragma unroll
        for (int slab = 0; slab < 6; slab++) {
            unsigned a0 = Qs[(slab*8+tig  )*136 + qw+grp];
            unsigned a1 = Qs[(slab*8+tig  )*136 + qw+grp+8];
            unsigned a2 = Qs[(slab*8+tig+4)*136 + qw+grp];
            unsigned a3 = Qs[(slab*8+tig+4)*136 + qw+grp+8];
            #pragma unroll
            for (int ni = 0; ni < 16; ni++) {
                unsigned b0 = Ks[(slab*8+tig  )*136 + ni*8+grp];
                unsigned b1 = Ks[(slab*8+tig+4)*136 + ni*8+grp];
                mma_tf32(sacc[ni], a0, a1, a2, a3, b0, b1);
            }
        }
        int r = (b*HH + h)*LQ + q0 + qw;
        float rm0 = g_rowm[r+grp],   iv0 = g_rowinv[r+grp];
        float rm1 = g_rowm[r+grp+8], iv1 = g_rowinv[r+grp+8];
        #pragma unroll
        for (int ni = 0; ni < 16; ni++) {
            bool mk0 = (mbits >> (2*ni)) & 1u;
            bool mk1 = (mbits >> (2*ni+1)) & 1u;
            float v0 = mk0 ? -1e30f : sacc[ni][0]*SCALE;
            float v1 = mk1 ? -1e30f : sacc[ni][1]*SCALE;
            float v2 = mk0 ? -1e30f : sacc[ni][2]*SCALE;
            float v3 = mk1 ? -1e30f : sacc[ni][3]*SCALE;
            aacc[ni][0] += __expf(v0 - rm0) * iv0;
            aacc[ni][1] += __expf(v1 - rm0) * iv0;
            aacc[ni][2] += __expf(v2 - rm1) * iv1;
            aacc[ni][3] += __expf(v3 - rm1) * iv1;
        }
    }
    const float invH = 1.f / (float)HH;
    #pragma unroll
    for (int ni = 0; ni < 16; ni++) {
        int k = k0g + ni*8 + 2*tig;
        float2 v0; v0.x = aacc[ni][0]*invH; v0.y = aacc[ni][1]*invH;
        *(float2*)&aw[((size_t)b*LQ + q0 + qw + grp) * LK + k] = v0;
        float2 v1; v1.x = aacc[ni][2]*invH; v1.y = aacc[ni][3]*invH;
        *(float2*)&aw[((size_t)b*LQ + q0 + qw + grp + 8) * LK + k] = v1;
    }
}

// ---------------- gate + residual + LayerNorm ----------------
__global__ __launch_bounds__(256)
void final_kernel(const float* __restrict__ query, const float* __restrict__ ln_g,
                  const float* __restrict__ ln_b, float* __restrict__ out) {
    int row = blockIdx.x;
    int b = row / LQ;
    float sf = g_sf[b], gv = g_gv[b];
    const float* qrow = query + (size_t)row * EE;
    const float* arow = g_attnout + (size_t)row * EE;
    __shared__ float sx[EE];
    __shared__ float sbuf[8], sbuf2[8];
    int tid = threadIdx.x;
    float lsum = 0.f, lsq = 0.f;
    for (int i = tid; i < EE; i += 256) {
        float qv = qrow[i];
        float gated = qv * (1.f - gv) + arow[i] * sf * gv;
        float x = qv + gated;
        sx[i] = x; lsum += x; lsq += x * x;
    }
    #pragma unroll
    for (int o = 16; o > 0; o >>= 1) {
        lsum += __shfl_xor_sync(0xffffffffu, lsum, o);
        lsq  += __shfl_xor_sync(0xffffffffu, lsq, o);
    }
    if ((tid & 31) == 0) { sbuf[tid >> 5] = lsum; sbuf2[tid >> 5] = lsq; }
    __syncthreads();
    float ts = 0.f, tq = 0.f;
    #pragma unroll
    for (int i = 0; i < 8; i++) { ts += sbuf[i]; tq += sbuf2[i]; }
    float mu = ts / (float)EE;
    float var = tq / (float)EE - mu * mu;
    float inv = rsqrtf(var + 1e-5f);
    float* orow = out + (size_t)row * EE;
    for (int i = tid; i < EE; i += 256)
        orow[i] = (sx[i] - mu) * inv * ln_g[i] + ln_b[i];
}

// ---------------- launch ----------------
extern "C" void kernel_launch(void* const* d_in, const int* in_sizes, int n_in,
                              void* d_out, int out_size) {
    const float* query = (const float*)d_in[0];
    const float* key   = (const float*)d_in[1];
    const float* value = (const float*)d_in[2];
    const unsigned char* mask = (const unsigned char*)d_in[3];
    const float* Wp1 = (const float*)d_in[4];
    const float* bp1 = (const float*)d_in[5];
    const float* Wp2 = (const float*)d_in[6];
    const float* bp2 = (const float*)d_in[7];
    const float* Wp3 = (const float*)d_in[8];
    const float* bp3 = (const float*)d_in[9];
    const float* inw = (const float*)d_in[10];
    const float* inb = (const float*)d_in[11];
    const float* outw = (const float*)d_in[12];
    const float* outb = (const float*)d_in[13];
    const float* lng = (const float*)d_in[14];
    const float* lnb = (const float*)d_in[15];

    float* out = (float*)d_out;
    float* out_output = out;
    float* out_aw = out + (size_t)BB * LQ * EE;
    float* out_tail = out_aw + (size_t)BB * LQ * LK;

    float *qp, *kp, *vp, *ctx, *aout;
    cudaGetSymbolAddress((void**)&qp, g_qp);
    cudaGetSymbolAddress((void**)&kp, g_kp);
    cudaGetSymbolAddress((void**)&vp, g_vp);
    cudaGetSymbolAddress((void**)&ctx, g_ctx);
    cudaGetSymbolAddress((void**)&aout, g_attnout);

    cudaFuncSetAttribute(flash_kernel, cudaFuncAttributeMaxDynamicSharedMemorySize, FL_SMEM);
    cudaFuncSetAttribute(attnmean2_kernel, cudaFuncAttributeMaxDynamicSharedMemorySize, AM_SMEM);

    mean_kernel<<<(BB*EE + 255)/256, 256>>>(query, LQ, 0);
    mean_kernel<<<(BB*EE + 255)/256, 256>>>(key,   LK, 1);
    mlp_kernel<<<BB, EE>>>(Wp1, bp1, Wp2, bp2, Wp3, bp3, out_tail);

    gemm_tf32_kernel<<<dim3(EE/128, MQ/128), 256>>>(query, inw,           inb,        qp,  MQ, EE, EE);
    gemm_tf32_kernel<<<dim3(EE/128, MK/128), 256>>>(key,   inw + EE*EE,   inb + EE,   kp,  MK, EE, EE);
    gemm_tf32_kernel<<<dim3(EE/128, MK/128), 256>>>(value, inw + 2*EE*EE, inb + 2*EE, vp,  MK, EE, EE);

    flash_kernel<<<dim3(LQ/128, BB*HH), 256, FL_SMEM>>>(mask);

    gemm_tf32_kernel<<<dim3(EE/128, MQ/128), 256>>>(ctx, outw, outb, aout, MQ, EE, EE);

    attnmean2_kernel<<<dim3(LK/128, LQ/128, BB), 256, AM_SMEM>>>(mask, out_aw);

    final_kernel<<<BB*LQ, 256>>>(query, lng, lnb, out_output);
}

// round 13
// speedup vs baseline: 1.0537x; 1.0537x over previous
#include <cuda_runtime.h>
#include <math.h>

#define BB 4
#define LQ 1024
#define LK 2048
#define EE 768
#define HH 16
#define HD 48
#define MQ (BB*LQ)
#define MK (BB*LK)
#define SPITCH 130
#define SCALE 0.14433756729740643f   /* 1/sqrt(48) */

// ---------------- static scratch ----------------
__device__ float g_qp[MQ*EE];
__device__ float g_kp[MK*EE];
__device__ float g_vp[MK*EE];
__device__ float g_ctx[MQ*EE];
__device__ float g_attnout[MQ*EE];
__device__ float g_qmean[BB*EE];
__device__ float g_kmean[BB*EE];
__device__ float g_sf[BB];
__device__ float g_gv[BB];
__device__ float g_rowm[BB*HH*LQ];
__device__ float g_rowinv[BB*HH*LQ];

// ---------------- tf32 helpers ----------------
__device__ __forceinline__ unsigned f2tf(float x) {
    unsigned r; asm("cvt.rna.tf32.f32 %0, %1;" : "=r"(r) : "f"(x)); return r;
}
__device__ __forceinline__ void mma_tf32(float* c, unsigned a0, unsigned a1, unsigned a2, unsigned a3,
                                         unsigned b0, unsigned b1) {
    asm volatile("mma.sync.aligned.m16n8k8.row.col.f32.tf32.tf32.f32 "
                 "{%0,%1,%2,%3},{%4,%5,%6,%7},{%8,%9},{%0,%1,%2,%3};"
                 : "+f"(c[0]), "+f"(c[1]), "+f"(c[2]), "+f"(c[3])
                 : "r"(a0), "r"(a1), "r"(a2), "r"(a3), "r"(b0), "r"(b1));
}

// ---------------- mean over sequence ----------------
__global__ void mean_kernel(const float* __restrict__ x, int L, int which) {
    int idx = blockIdx.x * blockDim.x + threadIdx.x;
    if (idx >= BB * EE) return;
    int b = idx / EE, e = idx % EE;
    const float* p = x + (size_t)b * L * EE + e;
    float s = 0.f;
    for (int l = 0; l < L; l++) s += p[(size_t)l * EE];
    (which ? g_kmean : g_qmean)[idx] = s / (float)L;
}

// ---------------- controller MLP ----------------
__global__ void mlp_kernel(const float* __restrict__ Wp1, const float* __restrict__ bp1,
                           const float* __restrict__ Wp2, const float* __restrict__ bp2,
                           const float* __restrict__ Wp3, const float* __restrict__ bp3,
                           float* __restrict__ out_tail) {
    int b = blockIdx.x;
    int t = threadIdx.x;
    __shared__ float pin[2*EE];
    __shared__ float sh1[EE];
    __shared__ float sh2[EE/2];
    __shared__ float spred[3];
    pin[t]      = g_qmean[b*EE + t];
    pin[EE + t] = g_kmean[b*EE + t];
    __syncthreads();
    {
        float acc = bp1[t];
        const float* w = Wp1 + (size_t)t * (2*EE);
        for (int j = 0; j < 2*EE; j++) acc = fmaf(pin[j], w[j], acc);
        sh1[t] = fmaxf(acc, 0.f);
    }
    __syncthreads();
    if (t < EE/2) {
        float acc = bp2[t];
        const float* w = Wp2 + (size_t)t * EE;
        for (int j = 0; j < EE; j++) acc = fmaf(sh1[j], w[j], acc);
        sh2[t] = fmaxf(acc, 0.f);
    }
    __syncthreads();
    if (t < 3) {
        float acc = bp3[t];
        const float* w = Wp3 + t * (EE/2);
        for (int j = 0; j < EE/2; j++) acc = fmaf(sh2[j], w[j], acc);
        spred[t] = acc;
    }
    __syncthreads();
    if (t == 0) {
        float s0 = 1.f / (1.f + expf(-spred[0]));
        float nh = rintf(s0 * (float)(HH - 1) + 1.f);
        float sf = (1.f / (1.f + expf(-spred[1]))) * 0.5f + 0.5f;
        float gv = 1.f / (1.f + expf(-spred[2]));
        g_sf[b] = sf; g_gv[b] = gv;
        out_tail[b]        = nh;
        out_tail[BB + b]   = sf;
        out_tail[2*BB + b] = gv;
    }
}

// ---------------- tf32 GEMM body (C = A @ W^T + bias) ----------------
__device__ __forceinline__ void gemm_body(const float* __restrict__ A, const float* __restrict__ W,
                                          const float* __restrict__ bias, float* __restrict__ C,
                                          int N, int K, int m0, int n0,
                                          unsigned (*As)[SPITCH], unsigned (*Bs)[SPITCH]) {
    const int tid = threadIdx.x;
    const int wid = tid >> 5, lane = tid & 31;
    const int grp = lane >> 2, tig = lane & 3;
    const int wm = wid & 1, wn = wid >> 1;
    const int row = tid >> 1, colh = (tid & 1) * 8;
    const float* Ap = A + (size_t)(m0 + row) * K + colh;
    const float* Wp = W + (size_t)(n0 + row) * K + colh;
    float acc[4][4][4] = {};
    const int T = K >> 4;
    float4 av0 = *(const float4*)Ap, av1 = *(const float4*)(Ap + 4);
    float4 wv0 = *(const float4*)Wp, wv1 = *(const float4*)(Wp + 4);
    int buf = 0;
    for (int t = 0; t < T; t++) {
        unsigned (*Ab)[SPITCH] = As + buf*16;
        unsigned (*Bb)[SPITCH] = Bs + buf*16;
        Ab[colh+0][row] = f2tf(av0.x); Ab[colh+1][row] = f2tf(av0.y);
        Ab[colh+2][row] = f2tf(av0.z); Ab[colh+3][row] = f2tf(av0.w);
        Ab[colh+4][row] = f2tf(av1.x); Ab[colh+5][row] = f2tf(av1.y);
        Ab[colh+6][row] = f2tf(av1.z); Ab[colh+7][row] = f2tf(av1.w);
        Bb[colh+0][row] = f2tf(wv0.x); Bb[colh+1][row] = f2tf(wv0.y);
        Bb[colh+2][row] = f2tf(wv0.z); Bb[colh+3][row] = f2tf(wv0.w);
        Bb[colh+4][row] = f2tf(wv1.x); Bb[colh+5][row] = f2tf(wv1.y);
        Bb[colh+6][row] = f2tf(wv1.z); Bb[colh+7][row] = f2tf(wv1.w);
        __syncthreads();
        if (t + 1 < T) {
            av0 = *(const float4*)(Ap + (t+1)*16); av1 = *(const float4*)(Ap + (t+1)*16 + 4);
            wv0 = *(const float4*)(Wp + (t+1)*16); wv1 = *(const float4*)(Wp + (t+1)*16 + 4);
        }
        #pragma unroll
        for (int ks = 0; ks < 2; ks++) {
            const int k0 = ks * 8;
            unsigned af[4][4], bf[4][2];
            #pragma unroll
            for (int mi = 0; mi < 4; mi++) {
                int m = wm*64 + mi*16;
                af[mi][0] = Ab[k0+tig  ][m+grp];
                af[mi][1] = Ab[k0+tig  ][m+grp+8];
                af[mi][2] = Ab[k0+tig+4][m+grp];
                af[mi][3] = Ab[k0+tig+4][m+grp+8];
            }
            #pragma unroll
            for (int ni = 0; ni < 4; ni++) {
                int n = wn*32 + ni*8;
                bf[ni][0] = Bb[k0+tig  ][n+grp];
                bf[ni][1] = Bb[k0+tig+4][n+grp];
            }
            #pragma unroll
            for (int mi = 0; mi < 4; mi++)
                #pragma unroll
                for (int ni = 0; ni < 4; ni++)
                    mma_tf32(acc[mi][ni], af[mi][0], af[mi][1], af[mi][2], af[mi][3],
                             bf[ni][0], bf[ni][1]);
        }
        buf ^= 1;
        __syncthreads();
    }
    #pragma unroll
    for (int mi = 0; mi < 4; mi++) {
        int m = m0 + wm*64 + mi*16 + grp;
        #pragma unroll
        for (int ni = 0; ni < 4; ni++) {
            int n = n0 + wn*32 + ni*8 + 2*tig;
            float b0 = bias[n], b1 = bias[n+1];
            float2 o;
            o.x = acc[mi][ni][0] + b0; o.y = acc[mi][ni][1] + b1;
            *(float2*)&C[(size_t)m * N + n] = o;
            o.x = acc[mi][ni][2] + b0; o.y = acc[mi][ni][3] + b1;
            *(float2*)&C[(size_t)(m+8) * N + n] = o;
        }
    }
}

// merged QKV projection: z selects (query->qp, key->kp, value->vp)
__global__ __launch_bounds__(256, 2)
void qkv_tf32_kernel(const float* __restrict__ query, const float* __restrict__ key,
                     const float* __restrict__ value, const float* __restrict__ inw,
                     const float* __restrict__ inb) {
    __shared__ unsigned As[2*16][SPITCH];
    __shared__ unsigned Bs[2*16][SPITCH];
    const int z = blockIdx.z;
    const int M = (z == 0) ? MQ : MK;
    if ((int)blockIdx.y * 128 >= M) return;
    const float* A = (z == 0) ? query : ((z == 1) ? key : value);
    const float* W = inw + (size_t)z * EE * EE;
    const float* bias = inb + z * EE;
    float* C = (z == 0) ? g_qp : ((z == 1) ? g_kp : g_vp);
    gemm_body(A, W, bias, C, EE, EE, blockIdx.y * 128, blockIdx.x * 128, As, Bs);
}

// out projection
__global__ __launch_bounds__(256, 2)
void gemm_tf32_kernel(const float* __restrict__ A, const float* __restrict__ W,
                      const float* __restrict__ bias, float* __restrict__ C,
                      int M, int N, int K) {
    __shared__ unsigned As[2*16][SPITCH];
    __shared__ unsigned Bs[2*16][SPITCH];
    gemm_body(A, W, bias, C, N, K, blockIdx.y * 128, blockIdx.x * 128, As, Bs);
}

// ================= FLASH ATTENTION v2: Q in registers, halved P staging =================
// smem words: Ks [48][136] @0 (6528) | Vs [128][56] @6528 (7168) | Ps [128][68] @13696 (8704) | Ms @22400
#define FK_KS 0
#define FK_VS 6528
#define FK_PS 13696
#define FK_MS 22400
#define FK_SMEM ((22400 + 32) * 4)

__global__ __launch_bounds__(256, 2)
void flash2_kernel(const unsigned char* __restrict__ mask) {
    extern __shared__ unsigned sm[];
    unsigned* Ks = sm + FK_KS;
    unsigned* Vs = sm + FK_VS;
    unsigned* Ps = sm + FK_PS;
    unsigned char* Ms = (unsigned char*)(sm + FK_MS);

    const int bh = blockIdx.y, b = bh >> 4, h = bh & 15;
    const int q0 = blockIdx.x * 128;
    const int tid = threadIdx.x;
    const int wid = tid >> 5, lane = tid & 31;
    const int grp = lane >> 2, tig = lane & 3;
    const int qw = wid * 16;

    // Q as A-fragments in registers (rows qw+grp / qw+grp+8, cols slab*8 + {tig, tig+4})
    unsigned qa[6][4];
    {
        const float* qb = g_qp + (size_t)(b*LQ + q0 + qw) * EE + h*HD;
        #pragma unroll
        for (int s = 0; s < 6; s++) {
            qa[s][0] = f2tf(qb[(size_t)grp     * EE + s*8 + tig]);
            qa[s][1] = f2tf(qb[(size_t)(grp+8) * EE + s*8 + tig]);
            qa[s][2] = f2tf(qb[(size_t)grp     * EE + s*8 + tig + 4]);
            qa[s][3] = f2tf(qb[(size_t)(grp+8) * EE + s*8 + tig + 4]);
        }
    }

    float o[6][4] = {};
    float m0 = -3.4e38f, m1 = -3.4e38f;
    float s0 = 0.f, s1 = 0.f;

    for (int kt = 0; kt < LK/128; kt++) {
        __syncthreads();
        const float* kb = g_kp + (size_t)(b*LK + kt*128) * EE + h*HD;
        const float* vb = g_vp + (size_t)(b*LK + kt*128) * EE + h*HD;
        for (int i = tid; i < 128*12; i += 256) {
            int k = i & 127, dc = i >> 7;
            float4 v = *(const float4*)(kb + (size_t)k * EE + dc*4);
            Ks[(dc*4+0)*136 + k] = f2tf(v.x);
            Ks[(dc*4+1)*136 + k] = f2tf(v.y);
            Ks[(dc*4+2)*136 + k] = f2tf(v.z);
            Ks[(dc*4+3)*136 + k] = f2tf(v.w);
            float4 w = *(const float4*)(vb + (size_t)k * EE + dc*4);
            Vs[k*56 + dc*4+0] = f2tf(w.x);
            Vs[k*56 + dc*4+1] = f2tf(w.y);
            Vs[k*56 + dc*4+2] = f2tf(w.z);
            Vs[k*56 + dc*4+3] = f2tf(w.w);
        }
        if (tid < 128) Ms[tid] = mask[b*LK + kt*128 + tid];
        __syncthreads();

        // S = Q @ K^T (A from registers)
        float sacc[16][4] = {};
        #pragma unroll
        for (int slab = 0; slab < 6; slab++) {
            #pragma unroll
            for (int ni = 0; ni < 16; ni++) {
                unsigned b0 = Ks[(slab*8+tig  )*136 + ni*8+grp];
                unsigned b1 = Ks[(slab*8+tig+4)*136 + ni*8+grp];
                mma_tf32(sacc[ni], qa[slab][0], qa[slab][1], qa[slab][2], qa[slab][3], b0, b1);
            }
        }

        // scale + mask + tile max
        float tm0 = -3.4e38f, tm1 = -3.4e38f;
        #pragma unroll
        for (int ni = 0; ni < 16; ni++) {
            int kc = ni*8 + 2*tig;
            bool mk0 = Ms[kc], mk1 = Ms[kc+1];
            sacc[ni][0] = mk0 ? -1e30f : sacc[ni][0]*SCALE;
            sacc[ni][1] = mk1 ? -1e30f : sacc[ni][1]*SCALE;
            sacc[ni][2] = mk0 ? -1e30f : sacc[ni][2]*SCALE;
            sacc[ni][3] = mk1 ? -1e30f : sacc[ni][3]*SCALE;
            tm0 = fmaxf(tm0, fmaxf(sacc[ni][0], sacc[ni][1]));
            tm1 = fmaxf(tm1, fmaxf(sacc[ni][2], sacc[ni][3]));
        }
        tm0 = fmaxf(tm0, __shfl_xor_sync(0xffffffffu, tm0, 1));
        tm0 = fmaxf(tm0, __shfl_xor_sync(0xffffffffu, tm0, 2));
        tm1 = fmaxf(tm1, __shfl_xor_sync(0xffffffffu, tm1, 1));
        tm1 = fmaxf(tm1, __shfl_xor_sync(0xffffffffu, tm1, 2));

        float mn0 = fmaxf(m0, tm0), mn1 = fmaxf(m1, tm1);
        float f0 = __expf(m0 - mn0), f1 = __expf(m1 - mn1);
        m0 = mn0; m1 = mn1;
        s0 *= f0; s1 *= f1;
        #pragma unroll
        for (int ni = 0; ni < 6; ni++) {
            o[ni][0] *= f0; o[ni][1] *= f0;
            o[ni][2] *= f1; o[ni][3] *= f1;
        }

        // two halves: stage P (64 cols), MMA against V half
        #pragma unroll
        for (int hh = 0; hh < 2; hh++) {
            float ps0 = 0.f, ps1 = 0.f;
            #pragma unroll
            for (int nl = 0; nl < 8; nl++) {
                int ni = hh*8 + nl;
                float p0 = __expf(sacc[ni][0] - mn0);
                float p1 = __expf(sacc[ni][1] - mn0);
                float p2 = __expf(sacc[ni][2] - mn1);
                float p3 = __expf(sacc[ni][3] - mn1);
                ps0 += p0 + p1; ps1 += p2 + p3;
                int kc = nl*8 + 2*tig;
                Ps[(qw+grp  )*68 + kc  ] = f2tf(p0);
                Ps[(qw+grp  )*68 + kc+1] = f2tf(p1);
                Ps[(qw+grp+8)*68 + kc  ] = f2tf(p2);
                Ps[(qw+grp+8)*68 + kc+1] = f2tf(p3);
            }
            s0 += ps0; s1 += ps1;
            __syncthreads();
            #pragma unroll
            for (int s = 0; s < 8; s++) {
                unsigned a0 = Ps[(qw+grp  )*68 + s*8+tig];
                unsigned a1 = Ps[(qw+grp+8)*68 + s*8+tig];
                unsigned a2 = Ps[(qw+grp  )*68 + s*8+tig+4];
                unsigned a3 = Ps[(qw+grp+8)*68 + s*8+tig+4];
                int kg = hh*64 + s*8;
                #pragma unroll
                for (int ni = 0; ni < 6; ni++) {
                    unsigned b0 = Vs[(kg+tig  )*56 + ni*8+grp];
                    unsigned b1 = Vs[(kg+tig+4)*56 + ni*8+grp];
                    mma_tf32(o[ni], a0, a1, a2, a3, b0, b1);
                }
            }
            __syncthreads();
        }
    }

    s0 += __shfl_xor_sync(0xffffffffu, s0, 1);
    s0 += __shfl_xor_sync(0xffffffffu, s0, 2);
    s1 += __shfl_xor_sync(0xffffffffu, s1, 1);
    s1 += __shfl_xor_sync(0xffffffffu, s1, 2);
    float inv0 = 1.f / s0, inv1 = 1.f / s1;

    float* cb = g_ctx + (size_t)(b*LQ + q0 + qw) * EE + h*HD;
    #pragma unroll
    for (int ni = 0; ni < 6; ni++) {
        int d = ni*8 + 2*tig;
        float2 v0; v0.x = o[ni][0]*inv0; v0.y = o[ni][1]*inv0;
        *(float2*)&cb[(size_t)grp * EE + d] = v0;
        float2 v1; v1.x = o[ni][2]*inv1; v1.y = o[ni][3]*inv1;
        *(float2*)&cb[(size_t)(grp+8) * EE + d] = v1;
    }
    if (tig == 0) {
        int r = bh*LQ + q0 + qw;
        g_rowm[r+grp]     = m0;  g_rowinv[r+grp]     = inv0;
        g_rowm[r+grp+8]   = m1;  g_rowinv[r+grp+8]   = inv1;
    }
}

// ================= attn_weights: recompute scores, mean over heads =================
#define AM_SMEM ((6528*2) * 4)
__global__ __launch_bounds__(256)
void attnmean2_kernel(const unsigned char* __restrict__ mask, float* __restrict__ aw) {
    extern __shared__ unsigned sm[];
    unsigned* Qs = sm;
    unsigned* Ks = sm + 6528;
    const int b = blockIdx.z;
    const int q0 = blockIdx.y * 128, k0g = blockIdx.x * 128;
    const int tid = threadIdx.x;
    const int wid = tid >> 5, lane = tid & 31;
    const int grp = lane >> 2, tig = lane & 3;
    const int qw = wid * 16;

    unsigned mbits = 0;
    #pragma unroll
    for (int ni = 0; ni < 16; ni++) {
        int kc = k0g + ni*8 + 2*tig;
        if (mask[b*LK + kc  ]) mbits |= 1u << (2*ni);
        if (mask[b*LK + kc+1]) mbits |= 1u << (2*ni+1);
    }

    float aacc[16][4] = {};
    for (int h = 0; h < HH; h++) {
        __syncthreads();
        const float* qb = g_qp + (size_t)(b*LQ + q0) * EE + h*HD;
        const float* kb = g_kp + (size_t)(b*LK + k0g) * EE + h*HD;
        for (int i = tid; i < 128*12; i += 256) {
            int r = i & 127, dc = i >> 7;
            float4 v = *(const float4*)(qb + (size_t)r * EE + dc*4);
            Qs[(dc*4+0)*136 + r] = f2tf(v.x);
            Qs[(dc*4+1)*136 + r] = f2tf(v.y);
            Qs[(dc*4+2)*136 + r] = f2tf(v.z);
            Qs[(dc*4+3)*136 + r] = f2tf(v.w);
            float4 w = *(const float4*)(kb + (size_t)r * EE + dc*4);
            Ks[(dc*4+0)*136 + r] = f2tf(w.x);
            Ks[(dc*4+1)*136 + r] = f2tf(w.y);
            Ks[(dc*4+2)*136 + r] = f2tf(w.z);
            Ks[(dc*4+3)*136 + r] = f2tf(w.w);
        }
        __syncthreads();

        float sacc[16][4] = {};
        #pragma unroll
        for (int slab = 0; slab < 6; slab++) {
            unsigned a0 = Qs[(slab*8+tig  )*136 + qw+grp];
            unsigned a1 = Qs[(slab*8+tig  )*136 + qw+grp+8];
            unsigned a2 = Qs[(slab*8+tig+4)*136 + qw+grp];
            unsigned a3 = Qs[(slab*8+tig+4)*136 + qw+grp+8];
            #pragma unroll
            for (int ni = 0; ni < 16; ni++) {
                unsigned b0 = Ks[(slab*8+tig  )*136 + ni*8+grp];
                unsigned b1 = Ks[(slab*8+tig+4)*136 + ni*8+grp];
                mma_tf32(sacc[ni], a0, a1, a2, a3, b0, b1);
            }
        }
        int r = (b*HH + h)*LQ + q0 + qw;
        float rm0 = g_rowm[r+grp],   iv0 = g_rowinv[r+grp];
        float rm1 = g_rowm[r+grp+8], iv1 = g_rowinv[r+grp+8];
        #pragma unroll
        for (int ni = 0; ni < 16; ni++) {
            bool mk0 = (mbits >> (2*ni)) & 1u;
            bool mk1 = (mbits >> (2*ni+1)) & 1u;
            float v0 = mk0 ? -1e30f : sacc[ni][0]*SCALE;
            float v1 = mk1 ? -1e30f : sacc[ni][1]*SCALE;
            float v2 = mk0 ? -1e30f : sacc[ni][2]*SCALE;
            float v3 = mk1 ? -1e30f : sacc[ni][3]*SCALE;
            aacc[ni][0] += __expf(v0 - rm0) * iv0;
            aacc[ni][1] += __expf(v1 - rm0) * iv0;
            aacc[ni][2] += __expf(v2 - rm1) * iv1;
            aacc[ni][3] += __expf(v3 - rm1) * iv1;
        }
    }
    const float invH = 1.f / (float)HH;
    #pragma unroll
    for (int ni = 0; ni < 16; ni++) {
        int k = k0g + ni*8 + 2*tig;
        float2 v0; v0.x = aacc[ni][0]*invH; v0.y = aacc[ni][1]*invH;
        *(float2*)&aw[((size_t)b*LQ + q0 + qw + grp) * LK + k] = v0;
        float2 v1; v1.x = aacc[ni][2]*invH; v1.y = aacc[ni][3]*invH;
        *(float2*)&aw[((size_t)b*LQ + q0 + qw + grp + 8) * LK + k] = v1;
    }
}

// ---------------- gate + residual + LayerNorm ----------------
__global__ __launch_bounds__(256)
void final_kernel(const float* __restrict__ query, const float* __restrict__ ln_g,
                  const float* __restrict__ ln_b, float* __restrict__ out) {
    int row = blockIdx.x;
    int b = row / LQ;
    float sf = g_sf[b], gv = g_gv[b];
    const float* qrow = query + (size_t)row * EE;
    const float* arow = g_attnout + (size_t)row * EE;
    __shared__ float sx[EE];
    __shared__ float sbuf[8], sbuf2[8];
    int tid = threadIdx.x;
    float lsum = 0.f, lsq = 0.f;
    for (int i = tid; i < EE; i += 256) {
        float qv = qrow[i];
        float gated = qv * (1.f - gv) + arow[i] * sf * gv;
        float x = qv + gated;
        sx[i] = x; lsum += x; lsq += x * x;
    }
    #pragma unroll
    for (int o = 16; o > 0; o >>= 1) {
        lsum += __shfl_xor_sync(0xffffffffu, lsum, o);
        lsq  += __shfl_xor_sync(0xffffffffu, lsq, o);
    }
    if ((tid & 31) == 0) { sbuf[tid >> 5] = lsum; sbuf2[tid >> 5] = lsq; }
    __syncthreads();
    float ts = 0.f, tq = 0.f;
    #pragma unroll
    for (int i = 0; i < 8; i++) { ts += sbuf[i]; tq += sbuf2[i]; }
    float mu = ts / (float)EE;
    float var = tq / (float)EE - mu * mu;
    float inv = rsqrtf(var + 1e-5f);
    float* orow = out + (size_t)row * EE;
    for (int i = tid; i < EE; i += 256)
        orow[i] = (sx[i] - mu) * inv * ln_g[i] + ln_b[i];
}

// ---------------- launch ----------------
extern "C" void kernel_launch(void* const* d_in, const int* in_sizes, int n_in,
                              void* d_out, int out_size) {
    const float* query = (const float*)d_in[0];
    const float* key   = (const float*)d_in[1];
    const float* value = (const float*)d_in[2];
    const unsigned char* mask = (const unsigned char*)d_in[3];
    const float* Wp1 = (const float*)d_in[4];
    const float* bp1 = (const float*)d_in[5];
    const float* Wp2 = (const float*)d_in[6];
    const float* bp2 = (const float*)d_in[7];
    const float* Wp3 = (const float*)d_in[8];
    const float* bp3 = (const float*)d_in[9];
    const float* inw = (const float*)d_in[10];
    const float* inb = (const float*)d_in[11];
    const float* outw = (const float*)d_in[12];
    const float* outb = (const float*)d_in[13];
    const float* lng = (const float*)d_in[14];
    const float* lnb = (const float*)d_in[15];

    float* out = (float*)d_out;
    float* out_output = out;
    float* out_aw = out + (size_t)BB * LQ * EE;
    float* out_tail = out_aw + (size_t)BB * LQ * LK;

    float *ctx, *aout;
    cudaGetSymbolAddress((void**)&ctx, g_ctx);
    cudaGetSymbolAddress((void**)&aout, g_attnout);

    cudaFuncSetAttribute(flash2_kernel, cudaFuncAttributeMaxDynamicSharedMemorySize, FK_SMEM);
    cudaFuncSetAttribute(attnmean2_kernel, cudaFuncAttributeMaxDynamicSharedMemorySize, AM_SMEM);

    mean_kernel<<<(BB*EE + 255)/256, 256>>>(query, LQ, 0);
    mean_kernel<<<(BB*EE + 255)/256, 256>>>(key,   LK, 1);
    mlp_kernel<<<BB, EE>>>(Wp1, bp1, Wp2, bp2, Wp3, bp3, out_tail);

    qkv_tf32_kernel<<<dim3(EE/128, MK/128, 3), 256>>>(query, key, value, inw, inb);

    flash2_kernel<<<dim3(LQ/128, BB*HH), 256, FK_SMEM>>>(mask);

    gemm_tf32_kernel<<<dim3(EE/128, MQ/128), 256>>>(ctx, outw, outb, aout, MQ, EE, EE);

    attnmean2_kernel<<<dim3(LK/128, LQ/128, BB), 256, AM_SMEM>>>(mask, out_aw);

    final_kernel<<<BB*LQ, 256>>>(query, lng, lnb, out_output);
}